// round 14
// baseline (speedup 1.0000x reference)
#include <cuda_runtime.h>
#include <cuda_bf16.h>
#include <math.h>

// Problem constants
#define BB 32
#define NN 1000
#define CC 64
#define HF 12
#define WF 20
#define DD 768          // C*HF
#define NM1 999         // N-1
#define YD 72
#define OUTC 77         // 2 + 2 + 73
#define HN 75           // heads output cols (2 cls + 73 reg)
#define BTPAD 1000      // padded attn_w row stride

// GEMM smem layout (floats) — 3 pipeline stages
#define SA_STRIDE 36            // 32 k + 4 pad
#define SB_STRIDE 136           // 128 n + 8 pad
#define SA_STAGE  (128 * SA_STRIDE)   // 4608
#define SB_STAGE  (32 * SB_STRIDE)    // 4352
#define SB_BASE   (3 * SA_STAGE)      // 13824
#define GEMM_SMEM ((3 * SA_STAGE + 3 * SB_STAGE) * 4)   // 107520 bytes

// ---------------------------------------------------------------------------
// Scratch (device globals; no runtime allocation allowed)
// ---------------------------------------------------------------------------
__device__ float g_feat[BB * NN * DD];        // (B,N,768) tf32-rounded
__device__ float g_logits[BB * NN * NM1];     // (B,N,999) fp32
__device__ float g_S[BB * NN * NN];           // (B,N,N) tf32-rounded softmax
__device__ float g_att[BB * NN * DD];         // (B,N,768) tf32-rounded
__device__ float g_ho[BB * NN * HN];          // heads GEMM result (32000 x 75)
__device__ float g_W[2 * DD * HN];            // packed [cls_w|reg_w], tf32-rounded
__device__ float g_Bt[DD * BTPAD];            // attn_w padded + rounded
__device__ int   g_mask_mode;                 // 1 = byte mask, 0 = 4-byte mask

// ---------------------------------------------------------------------------
// PTX helpers
// ---------------------------------------------------------------------------
__device__ __forceinline__ unsigned int smem_u32(const void* p)
{
    unsigned int a;
    asm("{ .reg .u64 t; cvta.to.shared.u64 t, %1; cvt.u32.u64 %0, t; }"
        : "=r"(a) : "l"(p));
    return a;
}

__device__ __forceinline__ void cp_async16(unsigned int dst, const void* src, int sz)
{
    asm volatile("cp.async.ca.shared.global [%0], [%1], 16, %2;"
                 :: "r"(dst), "l"(src), "r"(sz));
}

__device__ __forceinline__ void cp_async4(unsigned int dst, const void* src, int sz)
{
    asm volatile("cp.async.ca.shared.global [%0], [%1], 4, %2;"
                 :: "r"(dst), "l"(src), "r"(sz));
}

__device__ __forceinline__ void cp_commit()
{
    asm volatile("cp.async.commit_group;");
}

template<int N>
__device__ __forceinline__ void cp_wait()
{
    asm volatile("cp.async.wait_group %0;" :: "n"(N));
}

__device__ __forceinline__ float f2tf32f(float f)
{
    unsigned int r;
    asm("cvt.rna.tf32.f32 %0, %1;" : "=r"(r) : "f"(f));
    return __uint_as_float(r);
}

// ---------------------------------------------------------------------------
// Mask dtype detection (bool/uint8 vs int32/float32)
// ---------------------------------------------------------------------------
__global__ __launch_bounds__(256)
void detect_mask_kernel(const unsigned int* __restrict__ w, int nwords)
{
    __shared__ int bad;
    if (threadIdx.x == 0) bad = 0;
    __syncthreads();
    int local = 0;
    for (int k = threadIdx.x; k < nwords; k += blockDim.x) {
        unsigned int v = w[k];
        if (v != 0u && v != 1u && v != 0x3F800000u) local = 1;
    }
    if (local) bad = 1;
    __syncthreads();
    if (threadIdx.x == 0) g_mask_mode = bad;   // 1 => byte mask
}

// ---------------------------------------------------------------------------
// Gather (writes tf32-rounded feat)
// ---------------------------------------------------------------------------
__global__ __launch_bounds__(256)
void gather_kernel(const float* __restrict__ fv,
                   const int* __restrict__ z,
                   const int* __restrict__ y,
                   const int* __restrict__ x,
                   const void* __restrict__ mask,
                   float* __restrict__ feat,
                   int total)
{
    int idx = blockIdx.x * blockDim.x + threadIdx.x;
    if (idx >= total) return;
    int d = idx % DD;
    int rest = idx / DD;
    int n = rest % NN;
    int b = rest / NN;
    int nd = n * DD + d;

    bool inv;
    if (g_mask_mode)
        inv = ((const unsigned char*)mask)[nd] != 0;
    else
        inv = ((const unsigned int*)mask)[nd] != 0u;

    float v = 0.f;
    if (!inv) {
        int zz = z[nd], yy = y[nd], xx = x[nd];
        v = fv[((b * CC + zz) * HF + yy) * WF + xx];
    }
    feat[idx] = f2tf32f(v);
}

// ---------------------------------------------------------------------------
// Prep attn_w: pad 999 -> 1000 row stride + tf32 round.
// ---------------------------------------------------------------------------
__global__ __launch_bounds__(256)
void prep_attnw_kernel(const float* __restrict__ w, float* __restrict__ out)
{
    int idx = blockIdx.x * blockDim.x + threadIdx.x;
    if (idx >= DD * BTPAD) return;
    int k = idx / BTPAD, n = idx % BTPAD;
    out[idx] = (n < NM1) ? f2tf32f(w[k * NM1 + n]) : 0.f;
}

// ---------------------------------------------------------------------------
// Pack heads weights (tf32-rounded)
// ---------------------------------------------------------------------------
__global__ __launch_bounds__(256)
void pack_w_kernel(const float* __restrict__ cls_w,
                   const float* __restrict__ reg_w,
                   float* __restrict__ W)
{
    int idx = blockIdx.x * blockDim.x + threadIdx.x;
    if (idx >= 2 * DD * HN) return;
    int k = idx / HN, c = idx % HN;
    float v = (c < 2) ? cls_w[k * 2 + c] : reg_w[k * 73 + (c - 2)];
    W[idx] = f2tf32f(v);
}

// ---------------------------------------------------------------------------
// TF32 tensor-core GEMM, 128x128 block, Ktile 32, 128 threads, 4 warps,
// warp tile 64x64 (4 m16 x 8 n8).  Operands pre-rounded to tf32.
//   As[m][k] stride 36  (conflict-free fragment loads)
//   Bs[k][n] stride 136 (conflict-free fragment loads)
// 3-stage cp.async pipeline (always-commit: exactly 2 groups outstanding at
// each wait, so wait_group(1) guarantees the current tile).  One
// __syncthreads per K-tile.
// MODE 0: plain A (stride lda). MODE 1: concat A=[A1|A2] rows of DD each.
// VECB: 16B B copies (ldb%4==0). ROUND_OUT: tf32-round C before store.
// ---------------------------------------------------------------------------
template<int MODE, bool ADD_BIAS, bool VECB, bool ROUND_OUT>
__global__ __launch_bounds__(128, 2)
void gemm_tf32_cp_kernel(const float* __restrict__ A,
                         const float* __restrict__ A2,
                         const float* __restrict__ B,
                         const float* __restrict__ bias,
                         float* __restrict__ C,
                         int M, int N, int K, int lda, int ldb,
                         size_t sA, size_t sB, size_t sC)
{
    extern __shared__ float sm[];

    const int tid  = threadIdx.x;
    const int lane = tid & 31;
    const int wid  = tid >> 5;          // 0..3
    const int gid  = lane >> 2;         // 0..7
    const int tg   = lane & 3;          // 0..3
    const int wm   = (wid & 1) * 64;
    const int wn   = (wid >> 1) * 64;

    const int m0 = blockIdx.y * 128;
    const int n0 = blockIdx.x * 128;

    if (MODE == 0) A += (size_t)blockIdx.z * sA;
    B += (size_t)blockIdx.z * sB;
    C += (size_t)blockIdx.z * sC;

    const unsigned int smA_u = smem_u32(sm);
    const unsigned int smB_u = smem_u32(sm + SB_BASE);

    float acc[4][8][4];
    #pragma unroll
    for (int i = 0; i < 4; i++)
        #pragma unroll
        for (int j = 0; j < 8; j++)
            #pragma unroll
            for (int q = 0; q < 4; q++) acc[i][j][q] = 0.f;

    // ---- stage: cp.async A-tile and B-tile for kt into stage st
    auto stage = [&](int kt, int st) {
        unsigned int abase = smA_u + st * (SA_STAGE * 4);
        #pragma unroll
        for (int i = 0; i < 8; i++) {
            int c   = tid + i * 128;
            int m_l = c >> 3, kq = c & 7;
            int m = m0 + m_l, kg = kt + kq * 4;
            const float* src;
            int sz = 0;
            if (m < M && kg < K) {
                if (MODE == 1)
                    src = (kg < DD) ? &A[(size_t)m * DD + kg]
                                    : &A2[(size_t)m * DD + (kg - DD)];
                else
                    src = &A[(size_t)m * lda + kg];
                int rem = (K - kg) * 4;
                sz = rem < 16 ? rem : 16;
            } else {
                src = A;
            }
            cp_async16(abase + (m_l * SA_STRIDE + kq * 4) * 4, src, sz);
        }
        unsigned int bbase = smB_u + st * (SB_STAGE * 4);
        if (VECB) {
            #pragma unroll
            for (int i = 0; i < 8; i++) {
                int c   = tid + i * 128;
                int k_l = c >> 5, nq = c & 31;
                int kg = kt + k_l;
                const float* src = (kg < K) ? &B[(size_t)kg * ldb + n0 + nq * 4] : B;
                int sz = (kg < K) ? 16 : 0;
                cp_async16(bbase + (k_l * SB_STRIDE + nq * 4) * 4, src, sz);
            }
        } else {
            #pragma unroll
            for (int i = 0; i < 32; i++) {
                int c   = tid + i * 128;
                int k_l = c >> 7, n_l = c & 127;
                int kg = kt + k_l, n = n0 + n_l;
                bool ok = (kg < K) && (n < N);
                const float* src = ok ? &B[(size_t)kg * ldb + n] : B;
                cp_async4(bbase + (k_l * SB_STRIDE + n_l) * 4, src, ok ? 4 : 0);
            }
        }
    };

    auto compute = [&](int st) {
        const unsigned int* Ab = (const unsigned int*)(sm + st * SA_STAGE);
        const unsigned int* Bb = (const unsigned int*)(sm + SB_BASE + st * SB_STAGE);
        #pragma unroll
        for (int ks = 0; ks < 4; ks++) {
            const int k0 = ks * 8;
            unsigned int a[4][4], bf[8][2];
            #pragma unroll
            for (int mt = 0; mt < 4; mt++) {
                int ar = wm + mt * 16 + gid;
                a[mt][0] = Ab[ar       * SA_STRIDE + k0 + tg];
                a[mt][1] = Ab[(ar + 8) * SA_STRIDE + k0 + tg];
                a[mt][2] = Ab[ar       * SA_STRIDE + k0 + tg + 4];
                a[mt][3] = Ab[(ar + 8) * SA_STRIDE + k0 + tg + 4];
            }
            #pragma unroll
            for (int nt = 0; nt < 8; nt++) {
                int bc = wn + nt * 8 + gid;
                bf[nt][0] = Bb[(k0 + tg)     * SB_STRIDE + bc];
                bf[nt][1] = Bb[(k0 + tg + 4) * SB_STRIDE + bc];
            }
            #pragma unroll
            for (int mt = 0; mt < 4; mt++)
                #pragma unroll
                for (int nt = 0; nt < 8; nt++) {
                    asm volatile(
                        "mma.sync.aligned.m16n8k8.row.col.f32.tf32.tf32.f32 "
                        "{%0,%1,%2,%3}, {%4,%5,%6,%7}, {%8,%9}, {%0,%1,%2,%3};\n"
                        : "+f"(acc[mt][nt][0]), "+f"(acc[mt][nt][1]),
                          "+f"(acc[mt][nt][2]), "+f"(acc[mt][nt][3])
                        : "r"(a[mt][0]), "r"(a[mt][1]), "r"(a[mt][2]), "r"(a[mt][3]),
                          "r"(bf[nt][0]), "r"(bf[nt][1]));
                }
        }
    };

    // ---- 3-stage pipeline, one sync per tile, always-commit ----
    // Invariant: exactly 2 groups outstanding at each wait point, groups
    // complete in commit order, so wait_group(1) => current tile complete.
    stage(0, 0);
    cp_commit();
    stage(32, 1);          // K >= 64 for all our GEMMs
    cp_commit();

    int it = 0;
    for (int kt = 0; kt < K; kt += 32, it++) {
        cp_wait<1>();
        __syncthreads();   // also: all warps done reading buffer (it+2)%3
        int st = it % 3;
        if (kt + 64 < K)
            stage(kt + 64, (it + 2) % 3);
        cp_commit();       // empty group when nothing staged (keeps invariant)
        compute(st);
    }

    // ---- epilogue ----
    #pragma unroll
    for (int mt = 0; mt < 4; mt++) {
        #pragma unroll
        for (int nt = 0; nt < 8; nt++) {
            int row0 = m0 + wm + mt * 16 + gid;
            int col0 = n0 + wn + nt * 8 + tg * 2;
            #pragma unroll
            for (int q = 0; q < 4; q++) {
                int row = row0 + (q >> 1) * 8;
                int col = col0 + (q & 1);
                if (row < M && col < N) {
                    float v = acc[mt][nt][q];
                    if (ADD_BIAS) v += bias[col];
                    if (ROUND_OUT) v = f2tf32f(v);
                    C[(size_t)row * N + col] = v;
                }
            }
        }
    }
}

// ---------------------------------------------------------------------------
// Row softmax over 999 logits + scatter into (N x N) with zero diagonal.
// Output tf32-rounded (consumed only by GEMM2 A).
// ---------------------------------------------------------------------------
__global__ __launch_bounds__(256)
void softmax_scatter_kernel(const float* __restrict__ logits,
                            float* __restrict__ S)
{
    const int i = blockIdx.x;
    const int b = blockIdx.y;
    const float* __restrict__ row = logits + ((size_t)(b * NN + i)) * NM1;
    float* __restrict__ o = S + ((size_t)(b * NN + i)) * NN;

    __shared__ float sh[8];
    const int tid = threadIdx.x;
    const int lane = tid & 31, warp = tid >> 5;

    float rv[4];
    #pragma unroll
    for (int p = 0; p < 4; p++) {
        int k = tid + 256 * p;
        rv[p] = (k < NM1) ? row[k] : -1e30f;
    }

    float m = -1e30f;
    #pragma unroll
    for (int p = 0; p < 4; p++) m = fmaxf(m, rv[p]);
    #pragma unroll
    for (int off = 16; off; off >>= 1) m = fmaxf(m, __shfl_xor_sync(0xffffffffu, m, off));
    if (lane == 0) sh[warp] = m;
    __syncthreads();
    if (warp == 0) {
        float t = (lane < 8) ? sh[lane] : -1e30f;
        #pragma unroll
        for (int off = 16; off; off >>= 1) t = fmaxf(t, __shfl_xor_sync(0xffffffffu, t, off));
        if (lane == 0) sh[0] = t;
    }
    __syncthreads();
    m = sh[0];
    __syncthreads();

    float s = 0.f;
    float ev[4];
    #pragma unroll
    for (int p = 0; p < 4; p++) {
        int k = tid + 256 * p;
        float e = (k < NM1) ? __expf(rv[p] - m) : 0.f;
        ev[p] = e;
        s += e;
    }
    #pragma unroll
    for (int off = 16; off; off >>= 1) s += __shfl_xor_sync(0xffffffffu, s, off);
    if (lane == 0) sh[warp] = s;
    __syncthreads();
    if (warp == 0) {
        float t = (lane < 8) ? sh[lane] : 0.f;
        #pragma unroll
        for (int off = 16; off; off >>= 1) t += __shfl_xor_sync(0xffffffffu, t, off);
        if (lane == 0) sh[0] = t;
    }
    __syncthreads();
    const float inv = 1.f / sh[0];

    #pragma unroll
    for (int p = 0; p < 4; p++) {
        int k = tid + 256 * p;
        if (k < NM1) {
            int j = (k < i) ? k : k + 1;
            o[j] = f2tf32f(ev[p] * inv);
        }
    }
    if (tid == 0) o[i] = 0.f;
}

// ---------------------------------------------------------------------------
// Heads epilogue: out[r][c] from ho (32000 x 75), biases, anchors.
// ---------------------------------------------------------------------------
__global__ __launch_bounds__(256)
void heads_epilogue_kernel(const float* __restrict__ ho,
                           const float* __restrict__ cls_b,
                           const float* __restrict__ reg_b,
                           const float* __restrict__ anchors,
                           float* __restrict__ out)
{
    int idx = blockIdx.x * blockDim.x + threadIdx.x;
    if (idx >= BB * NN * OUTC) return;
    int c = idx % OUTC;
    int r = idx / OUTC;
    int n = r % NN;
    float v;
    if (c < 2)       v = ho[(size_t)r * HN + c] + cls_b[c];
    else if (c < 4)  v = anchors[n * OUTC + c];
    else             v = ho[(size_t)r * HN + (c - 2)] + reg_b[c - 4]
                         + anchors[n * OUTC + c];
    out[idx] = v;
}

// ---------------------------------------------------------------------------
// Launch
// ---------------------------------------------------------------------------
extern "C" void kernel_launch(void* const* d_in, const int* in_sizes, int n_in,
                              void* d_out, int out_size)
{
    const float* fv      = (const float*)d_in[0];
    const float* attn_w  = (const float*)d_in[1];
    const float* attn_b  = (const float*)d_in[2];
    const float* cls_w   = (const float*)d_in[3];
    const float* cls_b   = (const float*)d_in[4];
    const float* reg_w   = (const float*)d_in[5];
    const float* reg_b   = (const float*)d_in[6];
    const float* anchors = (const float*)d_in[7];
    const int*   z       = (const int*)d_in[8];
    const int*   y       = (const int*)d_in[9];
    const int*   x       = (const int*)d_in[10];
    const void*  mask    = d_in[11];
    float* out = (float*)d_out;

    float *feat, *logits, *S, *att, *ho, *W, *Bt;
    cudaGetSymbolAddress((void**)&feat,   g_feat);
    cudaGetSymbolAddress((void**)&logits, g_logits);
    cudaGetSymbolAddress((void**)&S,      g_S);
    cudaGetSymbolAddress((void**)&att,    g_att);
    cudaGetSymbolAddress((void**)&ho,     g_ho);
    cudaGetSymbolAddress((void**)&W,      g_W);
    cudaGetSymbolAddress((void**)&Bt,     g_Bt);

    static int attr_done = 0;
    if (!attr_done) {
        cudaFuncSetAttribute(gemm_tf32_cp_kernel<0, true,  true,  false>,
                             cudaFuncAttributeMaxDynamicSharedMemorySize, GEMM_SMEM);
        cudaFuncSetAttribute(gemm_tf32_cp_kernel<0, false, true,  true>,
                             cudaFuncAttributeMaxDynamicSharedMemorySize, GEMM_SMEM);
        cudaFuncSetAttribute(gemm_tf32_cp_kernel<1, false, false, false>,
                             cudaFuncAttributeMaxDynamicSharedMemorySize, GEMM_SMEM);
        attr_done = 1;
    }

    // 1) mask dtype detection
    detect_mask_kernel<<<1, 256>>>((const unsigned int*)mask, 190000);

    // 2) gather (tf32-rounded output)
    {
        int total = BB * NN * DD;
        gather_kernel<<<(total + 255) / 256, 256>>>(fv, z, y, x, mask, feat, total);
    }

    // 2b) prep attn_w (pad+round) and pack heads weights (round)
    prep_attnw_kernel<<<(DD * BTPAD + 255) / 256, 256>>>(attn_w, Bt);
    pack_w_kernel<<<(2 * DD * HN + 255) / 256, 256>>>(cls_w, reg_w, W);

    // 3) logits = feat @ attn_w + attn_b   (per batch 1000x999, K=768; padded B, vec)
    {
        dim3 grid((NM1 + 127) / 128, (NN + 127) / 128, BB);
        gemm_tf32_cp_kernel<0, true, true, false><<<grid, 128, GEMM_SMEM>>>(
            feat, nullptr, Bt, attn_b, logits,
            NN, NM1, DD, DD, BTPAD,
            (size_t)NN * DD, 0, (size_t)NN * NM1);
    }

    // 4) softmax + scatter (tf32-rounded output)
    {
        dim3 grid(NN, BB);
        softmax_scatter_kernel<<<grid, 256>>>(logits, S);
    }

    // 5) att = S @ feat   (per batch 1000x768, K=1000; vec B; tf32-rounded output)
    {
        dim3 grid((DD + 127) / 128, (NN + 127) / 128, BB);
        gemm_tf32_cp_kernel<0, false, true, true><<<grid, 128, GEMM_SMEM>>>(
            S, nullptr, feat, nullptr, att,
            NN, DD, NN, NN, DD,
            (size_t)NN * NN, (size_t)NN * DD, (size_t)NN * DD);
    }

    // 6) heads GEMM: [att|feat] (32000 x 1536) @ W (1536 x 75; scalar B)
    {
        dim3 grid(1, (BB * NN + 127) / 128, 1);
        gemm_tf32_cp_kernel<1, false, false, false><<<grid, 128, GEMM_SMEM>>>(
            att, feat, W, nullptr, ho,
            BB * NN, HN, 2 * DD, 0, HN,
            0, 0, 0);
    }

    // 7) heads epilogue
    {
        int total = BB * NN * OUTC;
        heads_epilogue_kernel<<<(total + 255) / 256, 256>>>(ho, cls_b, reg_b,
                                                            anchors, out);
    }
}

// round 16
// speedup vs baseline: 1.4104x; 1.4104x over previous
#include <cuda_runtime.h>
#include <cuda_fp16.h>
#include <math.h>

// Problem constants
#define BB 32
#define NN 1000
#define CC 64
#define HF 12
#define WF 20
#define DD 768          // C*HF
#define NM1 999         // N-1
#define YD 72
#define OUTC 77         // 2 + 2 + 73
#define HN 75           // heads output cols (2 cls + 73 reg)

// fp16 GEMM smem layout (halves)
#define HSTRIDE 40                      // 32 k + 8 pad (80B rows, conflict-free)
#define HSTAGE  (128 * HSTRIDE)         // 5120 halves = 10240 B per operand
// layout: A stage0, A stage1, B stage0, B stage1
#define HB_BASE (2 * HSTAGE)

// ---------------------------------------------------------------------------
// Scratch (device globals; no runtime allocation allowed)
// ---------------------------------------------------------------------------
__device__ __half g_feat[BB * NN * DD];       // (B,N,768) k-major fp16
__device__ __half g_featT[BB * DD * NN];      // (B,768,1000) n-major fp16
__device__ float  g_logits[BB * NN * NM1];    // fp32
__device__ __half g_S[BB * NN * NN];          // fp16 softmax, zero diag
__device__ __half g_att[BB * NN * DD];        // fp16
__device__ float  g_ho[BB * NN * HN];         // heads GEMM result fp32
__device__ __half g_WT[HN * 2 * DD];          // heads weights [75 x 1536] fp16
__device__ __half g_BtT[NM1 * DD];            // attn_w^T [999 x 768] fp16
__device__ int    g_mask_mode;

// ---------------------------------------------------------------------------
// PTX helpers
// ---------------------------------------------------------------------------
__device__ __forceinline__ unsigned int smem_u32(const void* p)
{
    unsigned int a;
    asm("{ .reg .u64 t; cvta.to.shared.u64 t, %1; cvt.u32.u64 %0, t; }"
        : "=r"(a) : "l"(p));
    return a;
}

__device__ __forceinline__ void cp_async16(unsigned int dst, const void* src, int sz)
{
    asm volatile("cp.async.ca.shared.global [%0], [%1], 16, %2;"
                 :: "r"(dst), "l"(src), "r"(sz));
}

__device__ __forceinline__ void cp_commit()
{
    asm volatile("cp.async.commit_group;");
}

template<int N>
__device__ __forceinline__ void cp_wait()
{
    asm volatile("cp.async.wait_group %0;" :: "n"(N));
}

// ---------------------------------------------------------------------------
// Mask dtype detection (bool/uint8 vs int32/float32)
// ---------------------------------------------------------------------------
__global__ __launch_bounds__(256)
void detect_mask_kernel(const unsigned int* __restrict__ w, int nwords)
{
    __shared__ int bad;
    if (threadIdx.x == 0) bad = 0;
    __syncthreads();
    int local = 0;
    for (int k = threadIdx.x; k < nwords; k += blockDim.x) {
        unsigned int v = w[k];
        if (v != 0u && v != 1u && v != 0x3F800000u) local = 1;
    }
    if (local) bad = 1;
    __syncthreads();
    if (threadIdx.x == 0) g_mask_mode = bad;   // 1 => byte mask
}

// ---------------------------------------------------------------------------
// Gather: feat fp16 [b,n,d]
// ---------------------------------------------------------------------------
__global__ __launch_bounds__(256)
void gather_kernel(const float* __restrict__ fv,
                   const int* __restrict__ z,
                   const int* __restrict__ y,
                   const int* __restrict__ x,
                   const void* __restrict__ mask,
                   __half* __restrict__ feat,
                   int total)
{
    int idx = blockIdx.x * blockDim.x + threadIdx.x;
    if (idx >= total) return;
    int d = idx % DD;
    int rest = idx / DD;
    int n = rest % NN;
    int b = rest / NN;
    int nd = n * DD + d;

    bool inv;
    if (g_mask_mode)
        inv = ((const unsigned char*)mask)[nd] != 0;
    else
        inv = ((const unsigned int*)mask)[nd] != 0u;

    float v = 0.f;
    if (!inv) {
        int zz = z[nd], yy = y[nd], xx = x[nd];
        v = fv[((b * CC + zz) * HF + yy) * WF + xx];
    }
    feat[idx] = __float2half(v);
}

// ---------------------------------------------------------------------------
// Tiled transpose fp16: feat [NN x DD] -> featT [DD x NN], per batch.
// ---------------------------------------------------------------------------
__global__ __launch_bounds__(256)
void transpose_kernel(const __half* __restrict__ in, __half* __restrict__ out)
{
    __shared__ __half tile[32][34];
    const int b = blockIdx.z;
    in  += (size_t)b * NN * DD;
    out += (size_t)b * DD * NN;
    const int d0 = blockIdx.x * 32;
    const int n0 = blockIdx.y * 32;
    const int tx = threadIdx.x & 31, ty = threadIdx.x >> 5;  // 32 x 8
    #pragma unroll
    for (int j = 0; j < 4; j++) {
        int n = n0 + ty + j * 8;
        if (n < NN) tile[ty + j * 8][tx] = in[(size_t)n * DD + d0 + tx];
    }
    __syncthreads();
    #pragma unroll
    for (int j = 0; j < 4; j++) {
        int d = d0 + ty + j * 8;
        int n = n0 + tx;
        if (n < NN) out[(size_t)d * NN + n] = tile[tx][ty + j * 8];
    }
}

// ---------------------------------------------------------------------------
// Prep attn_w transposed fp16: BtT[n][k] = fp16(attn_w[k][n]),  [999 x 768]
// ---------------------------------------------------------------------------
__global__ __launch_bounds__(256)
void prep_attnwT_kernel(const float* __restrict__ w, __half* __restrict__ out)
{
    int idx = blockIdx.x * blockDim.x + threadIdx.x;
    if (idx >= NM1 * DD) return;
    int n = idx / DD, k = idx % DD;
    out[idx] = __float2half(w[k * NM1 + n]);
}

// ---------------------------------------------------------------------------
// Pack heads weights transposed fp16: WT[c][k], c<75, k<1536
// ---------------------------------------------------------------------------
__global__ __launch_bounds__(256)
void pack_w_kernel(const float* __restrict__ cls_w,
                   const float* __restrict__ reg_w,
                   __half* __restrict__ WT)
{
    int idx = blockIdx.x * blockDim.x + threadIdx.x;
    if (idx >= HN * 2 * DD) return;
    int c = idx / (2 * DD), k = idx % (2 * DD);
    float v = (c < 2) ? cls_w[k * 2 + c] : reg_w[k * 73 + (c - 2)];
    WT[idx] = __float2half(v);
}

// ---------------------------------------------------------------------------
// FP16 tensor-core GEMM: C = A (MxK k-major) @ B (NxK k-major)^T
// 128x128 block, Ktile 32 (2 x k16 mma steps), 128 threads, 4 warps,
// warp tile 64x64.  mma.sync.m16n8k16.f32.f16.f16.f32, fp32 accumulate.
// Smem: A/B [row][k] stride 40 halves (80B, conflict-free 4B fragment loads).
// 2-stage cp.async pipeline, one __syncthreads per K-tile (R12-proven).
// MODE 0: plain A (stride lda). MODE 1: concat A=[A1|A2] rows of DD halves.
// OUT 0: fp32 C (+bias if ADD_BIAS).  OUT 1: fp16 C.
// KbA/KbB: valid k extents (8-aligned); zero-fill beyond.  K = Ktiles*32.
// ---------------------------------------------------------------------------
template<int MODE, bool ADD_BIAS, int OUT>
__global__ __launch_bounds__(128, 2)
void gemm_fp16_kernel(const __half* __restrict__ A,
                      const __half* __restrict__ A2,
                      const __half* __restrict__ B,
                      const float* __restrict__ bias,
                      void* __restrict__ Cv,
                      int M, int N, int Ktiles, int KbA, int KbB,
                      int lda, int ldb,
                      size_t sA, size_t sB, size_t sC)
{
    __shared__ __half sm[4 * HSTAGE];   // 40960 B

    const int tid  = threadIdx.x;
    const int lane = tid & 31;
    const int wid  = tid >> 5;          // 0..3
    const int gid  = lane >> 2;         // 0..7
    const int tg   = lane & 3;          // 0..3
    const int wm   = (wid & 1) * 64;
    const int wn   = (wid >> 1) * 64;

    const int m0 = blockIdx.y * 128;
    const int n0 = blockIdx.x * 128;

    if (MODE == 0) A += (size_t)blockIdx.z * sA;
    B += (size_t)blockIdx.z * sB;

    const unsigned int smA_u = smem_u32(sm);
    const unsigned int smB_u = smem_u32(sm + HB_BASE);

    float acc[4][8][4];
    #pragma unroll
    for (int i = 0; i < 4; i++)
        #pragma unroll
        for (int j = 0; j < 8; j++)
            #pragma unroll
            for (int q = 0; q < 4; q++) acc[i][j][q] = 0.f;

    // stage: A-tile and B-tile (each 128 rows x 32 halves = 512 16B chunks,
    // 4 per thread per operand)
    auto stage = [&](int kt, int st) {
        unsigned int abase = smA_u + st * (HSTAGE * 2);
        #pragma unroll
        for (int i = 0; i < 4; i++) {
            int c   = tid + i * 128;
            int row = c >> 2, kq = c & 3;
            int m = m0 + row, kg = kt + kq * 8;
            const __half* src = A;
            int sz = 0;
            if (m < M && kg < KbA) {
                if (MODE == 1)
                    src = (kg < DD) ? &A[(size_t)m * DD + kg]
                                    : &A2[(size_t)m * DD + (kg - DD)];
                else
                    src = &A[(size_t)m * lda + kg];
                sz = 16;
            }
            cp_async16(abase + (row * HSTRIDE + kq * 8) * 2, src, sz);
        }
        unsigned int bbase = smB_u + st * (HSTAGE * 2);
        #pragma unroll
        for (int i = 0; i < 4; i++) {
            int c   = tid + i * 128;
            int row = c >> 2, kq = c & 3;
            int n = n0 + row, kg = kt + kq * 8;
            const __half* src = B;
            int sz = 0;
            if (n < N && kg < KbB) {
                src = &B[(size_t)n * ldb + kg];
                sz = 16;
            }
            cp_async16(bbase + (row * HSTRIDE + kq * 8) * 2, src, sz);
        }
    };

    auto compute = [&](int st) {
        const __half* Ab = sm + st * HSTAGE;
        const __half* Bb = sm + HB_BASE + st * HSTAGE;
        #pragma unroll
        for (int ks = 0; ks < 2; ks++) {
            const int k0 = ks * 16;
            unsigned int a[4][4], bf[8][2];
            #pragma unroll
            for (int mt = 0; mt < 4; mt++) {
                int ar = wm + mt * 16 + gid;
                a[mt][0] = *(const unsigned int*)(Ab + ar       * HSTRIDE + k0 + tg * 2);
                a[mt][1] = *(const unsigned int*)(Ab + (ar + 8) * HSTRIDE + k0 + tg * 2);
                a[mt][2] = *(const unsigned int*)(Ab + ar       * HSTRIDE + k0 + tg * 2 + 8);
                a[mt][3] = *(const unsigned int*)(Ab + (ar + 8) * HSTRIDE + k0 + tg * 2 + 8);
            }
            #pragma unroll
            for (int nt = 0; nt < 8; nt++) {
                int bc = wn + nt * 8 + gid;
                bf[nt][0] = *(const unsigned int*)(Bb + bc * HSTRIDE + k0 + tg * 2);
                bf[nt][1] = *(const unsigned int*)(Bb + bc * HSTRIDE + k0 + tg * 2 + 8);
            }
            #pragma unroll
            for (int mt = 0; mt < 4; mt++)
                #pragma unroll
                for (int nt = 0; nt < 8; nt++) {
                    asm volatile(
                        "mma.sync.aligned.m16n8k16.row.col.f32.f16.f16.f32 "
                        "{%0,%1,%2,%3}, {%4,%5,%6,%7}, {%8,%9}, {%0,%1,%2,%3};\n"
                        : "+f"(acc[mt][nt][0]), "+f"(acc[mt][nt][1]),
                          "+f"(acc[mt][nt][2]), "+f"(acc[mt][nt][3])
                        : "r"(a[mt][0]), "r"(a[mt][1]), "r"(a[mt][2]), "r"(a[mt][3]),
                          "r"(bf[nt][0]), "r"(bf[nt][1]));
                }
        }
    };

    // ---- 2-stage pipeline, one sync per tile ----
    stage(0, 0);
    cp_commit();

    int st = 0;
    for (int t = 0; t < Ktiles; t++) {
        cp_wait<0>();
        __syncthreads();
        if (t + 1 < Ktiles) {
            stage((t + 1) * 32, st ^ 1);
            cp_commit();
        }
        compute(st);
        st ^= 1;
    }

    // ---- epilogue ----
    #pragma unroll
    for (int mt = 0; mt < 4; mt++) {
        #pragma unroll
        for (int nt = 0; nt < 8; nt++) {
            int row0 = m0 + wm + mt * 16 + gid;
            int col0 = n0 + wn + nt * 8 + tg * 2;
            #pragma unroll
            for (int q = 0; q < 4; q++) {
                int row = row0 + (q >> 1) * 8;
                int col = col0 + (q & 1);
                if (row < M && col < N) {
                    float v = acc[mt][nt][q];
                    if (ADD_BIAS) v += bias[col];
                    if (OUT == 0) {
                        ((float*)Cv)[(size_t)blockIdx.z * sC + (size_t)row * N + col] = v;
                    } else {
                        ((__half*)Cv)[(size_t)blockIdx.z * sC + (size_t)row * N + col] =
                            __float2half(v);
                    }
                }
            }
        }
    }
}

// ---------------------------------------------------------------------------
// Row softmax over 999 fp32 logits + scatter into fp16 (N x N), zero diagonal.
// ---------------------------------------------------------------------------
__global__ __launch_bounds__(256)
void softmax_scatter_kernel(const float* __restrict__ logits,
                            __half* __restrict__ S)
{
    const int i = blockIdx.x;
    const int b = blockIdx.y;
    const float* __restrict__ row = logits + ((size_t)(b * NN + i)) * NM1;
    __half* __restrict__ o = S + ((size_t)(b * NN + i)) * NN;

    __shared__ float sh[8];
    const int tid = threadIdx.x;
    const int lane = tid & 31, warp = tid >> 5;

    float rv[4];
    #pragma unroll
    for (int p = 0; p < 4; p++) {
        int k = tid + 256 * p;
        rv[p] = (k < NM1) ? row[k] : -1e30f;
    }

    float m = -1e30f;
    #pragma unroll
    for (int p = 0; p < 4; p++) m = fmaxf(m, rv[p]);
    #pragma unroll
    for (int off = 16; off; off >>= 1) m = fmaxf(m, __shfl_xor_sync(0xffffffffu, m, off));
    if (lane == 0) sh[warp] = m;
    __syncthreads();
    if (warp == 0) {
        float t = (lane < 8) ? sh[lane] : -1e30f;
        #pragma unroll
        for (int off = 16; off; off >>= 1) t = fmaxf(t, __shfl_xor_sync(0xffffffffu, t, off));
        if (lane == 0) sh[0] = t;
    }
    __syncthreads();
    m = sh[0];
    __syncthreads();

    float s = 0.f;
    float ev[4];
    #pragma unroll
    for (int p = 0; p < 4; p++) {
        int k = tid + 256 * p;
        float e = (k < NM1) ? __expf(rv[p] - m) : 0.f;
        ev[p] = e;
        s += e;
    }
    #pragma unroll
    for (int off = 16; off; off >>= 1) s += __shfl_xor_sync(0xffffffffu, s, off);
    if (lane == 0) sh[warp] = s;
    __syncthreads();
    if (warp == 0) {
        float t = (lane < 8) ? sh[lane] : 0.f;
        #pragma unroll
        for (int off = 16; off; off >>= 1) t += __shfl_xor_sync(0xffffffffu, t, off);
        if (lane == 0) sh[0] = t;
    }
    __syncthreads();
    const float inv = 1.f / sh[0];

    #pragma unroll
    for (int p = 0; p < 4; p++) {
        int k = tid + 256 * p;
        if (k < NM1) {
            int j = (k < i) ? k : k + 1;
            o[j] = __float2half(ev[p] * inv);
        }
    }
    if (tid == 0) o[i] = __float2half(0.f);
}

// ---------------------------------------------------------------------------
// Heads epilogue: out[r][c] from ho (32000 x 75), biases, anchors.
// ---------------------------------------------------------------------------
__global__ __launch_bounds__(256)
void heads_epilogue_kernel(const float* __restrict__ ho,
                           const float* __restrict__ cls_b,
                           const float* __restrict__ reg_b,
                           const float* __restrict__ anchors,
                           float* __restrict__ out)
{
    int idx = blockIdx.x * blockDim.x + threadIdx.x;
    if (idx >= BB * NN * OUTC) return;
    int c = idx % OUTC;
    int r = idx / OUTC;
    int n = r % NN;
    float v;
    if (c < 2)       v = ho[(size_t)r * HN + c] + cls_b[c];
    else if (c < 4)  v = anchors[n * OUTC + c];
    else             v = ho[(size_t)r * HN + (c - 2)] + reg_b[c - 4]
                         + anchors[n * OUTC + c];
    out[idx] = v;
}

// ---------------------------------------------------------------------------
// Launch
// ---------------------------------------------------------------------------
extern "C" void kernel_launch(void* const* d_in, const int* in_sizes, int n_in,
                              void* d_out, int out_size)
{
    const float* fv      = (const float*)d_in[0];
    const float* attn_w  = (const float*)d_in[1];
    const float* attn_b  = (const float*)d_in[2];
    const float* cls_w   = (const float*)d_in[3];
    const float* cls_b   = (const float*)d_in[4];
    const float* reg_w   = (const float*)d_in[5];
    const float* reg_b   = (const float*)d_in[6];
    const float* anchors = (const float*)d_in[7];
    const int*   z       = (const int*)d_in[8];
    const int*   y       = (const int*)d_in[9];
    const int*   x       = (const int*)d_in[10];
    const void*  mask    = d_in[11];
    float* out = (float*)d_out;

    __half *feat, *featT, *S, *att, *WT, *BtT;
    float *logits, *ho;
    cudaGetSymbolAddress((void**)&feat,   g_feat);
    cudaGetSymbolAddress((void**)&featT,  g_featT);
    cudaGetSymbolAddress((void**)&logits, g_logits);
    cudaGetSymbolAddress((void**)&S,      g_S);
    cudaGetSymbolAddress((void**)&att,    g_att);
    cudaGetSymbolAddress((void**)&ho,     g_ho);
    cudaGetSymbolAddress((void**)&WT,     g_WT);
    cudaGetSymbolAddress((void**)&BtT,    g_BtT);

    // 1) mask dtype detection
    detect_mask_kernel<<<1, 256>>>((const unsigned int*)mask, 190000);

    // 2) gather (fp16 feat)
    {
        int total = BB * NN * DD;
        gather_kernel<<<(total + 255) / 256, 256>>>(fv, z, y, x, mask, feat, total);
    }

    // 2b) transpose feat -> featT; attn_w^T; heads W^T (all fp16)
    {
        dim3 grid(DD / 32, (NN + 31) / 32, BB);
        transpose_kernel<<<grid, 256>>>(feat, featT);
    }
    prep_attnwT_kernel<<<(NM1 * DD + 255) / 256, 256>>>(attn_w, BtT);
    pack_w_kernel<<<(HN * 2 * DD + 255) / 256, 256>>>(cls_w, reg_w, WT);

    // 3) logits = feat @ attn_w + attn_b   (1000x999, K=768 -> 24 tiles; fp32 out)
    {
        dim3 grid((NM1 + 127) / 128, (NN + 127) / 128, BB);
        gemm_fp16_kernel<0, true, 0><<<grid, 128>>>(
            feat, nullptr, BtT, attn_b, (void*)logits,
            NN, NM1, DD / 32, DD, DD, DD, DD,
            (size_t)NN * DD, 0, (size_t)NN * NM1);
    }

    // 4) softmax + scatter (fp16 S)
    {
        dim3 grid(NN, BB);
        softmax_scatter_kernel<<<grid, 256>>>(logits, S);
    }

    // 5) att = S @ feat   (1000x768, K=1000 -> 32 tiles, zero-fill; fp16 out)
    {
        dim3 grid((DD + 127) / 128, (NN + 127) / 128, BB);
        gemm_fp16_kernel<0, false, 1><<<grid, 128>>>(
            S, nullptr, featT, nullptr, (void*)att,
            NN, DD, 32, NN, NN, NN, NN,
            (size_t)NN * NN, (size_t)DD * NN, (size_t)NN * DD);
    }

    // 6) heads GEMM: [att|feat] (32000 x 1536) @ WT^T (75 cols), K=1536 -> 48 tiles
    {
        dim3 grid(1, (BB * NN + 127) / 128, 1);
        gemm_fp16_kernel<1, false, 0><<<grid, 128>>>(
            att, feat, WT, nullptr, (void*)ho,
            BB * NN, HN, 48, 2 * DD, 2 * DD, 2 * DD, 2 * DD,
            0, 0, 0);
    }

    // 7) heads epilogue
    {
        int total = BB * NN * OUTC;
        heads_epilogue_kernel<<<(total + 255) / 256, 256>>>(ho, cls_b, reg_b,
                                                            anchors, out);
    }
}

// round 17
// speedup vs baseline: 1.4614x; 1.0362x over previous
#include <cuda_runtime.h>
#include <cuda_fp16.h>
#include <math.h>

// Problem constants
#define BB 32
#define NN 1000
#define CC 64
#define HF 12
#define WF 20
#define DD 768          // C*HF
#define NM1 999         // N-1
#define YD 72
#define OUTC 77         // 2 + 2 + 73
#define HN 75           // heads output cols (2 cls + 73 reg)

// fp16 GEMM smem layout (halves), Ktile = 64
#define KT 64
#define HSTRIDE 72                      // 64 k + 8 pad (144B rows, conflict-free)
#define HSTAGE  (128 * HSTRIDE)         // 9216 halves = 18432 B per operand-stage
#define HB_BASE (2 * HSTAGE)            // A stage0, A stage1, B stage0, B stage1
#define GSMEM   (4 * HSTAGE * 2)        // 73728 bytes dynamic smem

// ---------------------------------------------------------------------------
// Scratch (device globals; no runtime allocation allowed)
// ---------------------------------------------------------------------------
__device__ __half g_feat[BB * NN * DD];       // (B,N,768) k-major fp16
__device__ __half g_featT[BB * DD * NN];      // (B,768,1000) n-major fp16
__device__ float  g_logits[BB * NN * NM1];    // fp32
__device__ __half g_S[BB * NN * NN];          // fp16 softmax, zero diag
__device__ __half g_att[BB * NN * DD];        // fp16
__device__ float  g_ho[BB * NN * HN];         // heads GEMM result fp32
__device__ __half g_WT[HN * 2 * DD];          // heads weights [75 x 1536] fp16
__device__ __half g_BtT[NM1 * DD];            // attn_w^T [999 x 768] fp16
__device__ int    g_mask_mode;

// ---------------------------------------------------------------------------
// PTX helpers
// ---------------------------------------------------------------------------
__device__ __forceinline__ unsigned int smem_u32(const void* p)
{
    unsigned int a;
    asm("{ .reg .u64 t; cvta.to.shared.u64 t, %1; cvt.u32.u64 %0, t; }"
        : "=r"(a) : "l"(p));
    return a;
}

__device__ __forceinline__ void cp_async16(unsigned int dst, const void* src, int sz)
{
    asm volatile("cp.async.ca.shared.global [%0], [%1], 16, %2;"
                 :: "r"(dst), "l"(src), "r"(sz));
}

__device__ __forceinline__ void cp_commit()
{
    asm volatile("cp.async.commit_group;");
}

template<int N>
__device__ __forceinline__ void cp_wait()
{
    asm volatile("cp.async.wait_group %0;" :: "n"(N));
}

// ---------------------------------------------------------------------------
// Mask dtype detection (bool/uint8 vs int32/float32)
// ---------------------------------------------------------------------------
__global__ __launch_bounds__(256)
void detect_mask_kernel(const unsigned int* __restrict__ w, int nwords)
{
    __shared__ int bad;
    if (threadIdx.x == 0) bad = 0;
    __syncthreads();
    int local = 0;
    for (int k = threadIdx.x; k < nwords; k += blockDim.x) {
        unsigned int v = w[k];
        if (v != 0u && v != 1u && v != 0x3F800000u) local = 1;
    }
    if (local) bad = 1;
    __syncthreads();
    if (threadIdx.x == 0) g_mask_mode = bad;   // 1 => byte mask
}

// ---------------------------------------------------------------------------
// Gather: feat fp16 [b,n,d]
// ---------------------------------------------------------------------------
__global__ __launch_bounds__(256)
void gather_kernel(const float* __restrict__ fv,
                   const int* __restrict__ z,
                   const int* __restrict__ y,
                   const int* __restrict__ x,
                   const void* __restrict__ mask,
                   __half* __restrict__ feat,
                   int total)
{
    int idx = blockIdx.x * blockDim.x + threadIdx.x;
    if (idx >= total) return;
    int d = idx % DD;
    int rest = idx / DD;
    int n = rest % NN;
    int b = rest / NN;
    int nd = n * DD + d;

    bool inv;
    if (g_mask_mode)
        inv = ((const unsigned char*)mask)[nd] != 0;
    else
        inv = ((const unsigned int*)mask)[nd] != 0u;

    float v = 0.f;
    if (!inv) {
        int zz = z[nd], yy = y[nd], xx = x[nd];
        v = fv[((b * CC + zz) * HF + yy) * WF + xx];
    }
    feat[idx] = __float2half(v);
}

// ---------------------------------------------------------------------------
// Tiled transpose fp16: feat [NN x DD] -> featT [DD x NN], per batch.
// ---------------------------------------------------------------------------
__global__ __launch_bounds__(256)
void transpose_kernel(const __half* __restrict__ in, __half* __restrict__ out)
{
    __shared__ __half tile[32][34];
    const int b = blockIdx.z;
    in  += (size_t)b * NN * DD;
    out += (size_t)b * DD * NN;
    const int d0 = blockIdx.x * 32;
    const int n0 = blockIdx.y * 32;
    const int tx = threadIdx.x & 31, ty = threadIdx.x >> 5;  // 32 x 8
    #pragma unroll
    for (int j = 0; j < 4; j++) {
        int n = n0 + ty + j * 8;
        if (n < NN) tile[ty + j * 8][tx] = in[(size_t)n * DD + d0 + tx];
    }
    __syncthreads();
    #pragma unroll
    for (int j = 0; j < 4; j++) {
        int d = d0 + ty + j * 8;
        int n = n0 + tx;
        if (n < NN) out[(size_t)d * NN + n] = tile[tx][ty + j * 8];
    }
}

// ---------------------------------------------------------------------------
// Prep attn_w transposed fp16: BtT[n][k] = fp16(attn_w[k][n]),  [999 x 768]
// ---------------------------------------------------------------------------
__global__ __launch_bounds__(256)
void prep_attnwT_kernel(const float* __restrict__ w, __half* __restrict__ out)
{
    int idx = blockIdx.x * blockDim.x + threadIdx.x;
    if (idx >= NM1 * DD) return;
    int n = idx / DD, k = idx % DD;
    out[idx] = __float2half(w[k * NM1 + n]);
}

// ---------------------------------------------------------------------------
// Pack heads weights transposed fp16: WT[c][k], c<75, k<1536
// ---------------------------------------------------------------------------
__global__ __launch_bounds__(256)
void pack_w_kernel(const float* __restrict__ cls_w,
                   const float* __restrict__ reg_w,
                   __half* __restrict__ WT)
{
    int idx = blockIdx.x * blockDim.x + threadIdx.x;
    if (idx >= HN * 2 * DD) return;
    int c = idx / (2 * DD), k = idx % (2 * DD);
    float v = (c < 2) ? cls_w[k * 2 + c] : reg_w[k * 73 + (c - 2)];
    WT[idx] = __float2half(v);
}

// ---------------------------------------------------------------------------
// FP16 tensor-core GEMM: C = A (MxK k-major) @ B (NxK k-major)^T
// 128x128 block, Ktile 64 (4 x k16 mma steps), 128 threads, 4 warps,
// warp tile 64x64.  mma.sync.m16n8k16.f32.f16.f16.f32, fp32 accumulate.
// Smem: A/B [row][k] stride 72 halves (144B; bank=(4*gid+tg)%32, conflict-free).
// 2-stage cp.async pipeline, one __syncthreads per K-tile.
// Warp-uniform N guard skips fully-OOB nt blocks (B frags + MMAs) — big win
// for heads (N=75 inside a 128 tile) and GEMM1's last n-tile (N=999).
// MODE 0: plain A (stride lda). MODE 1: concat A=[A1|A2] rows of DD halves.
// OUT 0: fp32 C (+bias if ADD_BIAS).  OUT 1: fp16 C.
// KbA/KbB: valid k extents (8-aligned); zero-fill beyond.  K = Ktiles*64.
// ---------------------------------------------------------------------------
template<int MODE, bool ADD_BIAS, int OUT>
__global__ __launch_bounds__(128, 2)
void gemm_fp16_kernel(const __half* __restrict__ A,
                      const __half* __restrict__ A2,
                      const __half* __restrict__ B,
                      const float* __restrict__ bias,
                      void* __restrict__ Cv,
                      int M, int N, int Ktiles, int KbA, int KbB,
                      int lda, int ldb,
                      size_t sA, size_t sB, size_t sC)
{
    extern __shared__ __half sm[];

    const int tid  = threadIdx.x;
    const int lane = tid & 31;
    const int wid  = tid >> 5;          // 0..3
    const int gid  = lane >> 2;         // 0..7
    const int tg   = lane & 3;          // 0..3
    const int wm   = (wid & 1) * 64;
    const int wn   = (wid >> 1) * 64;

    const int m0 = blockIdx.y * 128;
    const int n0 = blockIdx.x * 128;

    if (MODE == 0) A += (size_t)blockIdx.z * sA;
    B += (size_t)blockIdx.z * sB;

    const unsigned int smA_u = smem_u32(sm);
    const unsigned int smB_u = smem_u32(sm + HB_BASE);

    float acc[4][8][4];
    #pragma unroll
    for (int i = 0; i < 4; i++)
        #pragma unroll
        for (int j = 0; j < 8; j++)
            #pragma unroll
            for (int q = 0; q < 4; q++) acc[i][j][q] = 0.f;

    // stage: A-tile and B-tile (each 128 rows x 64 halves = 1024 16B chunks,
    // 8 per thread per operand)
    auto stage = [&](int kt, int st) {
        unsigned int abase = smA_u + st * (HSTAGE * 2);
        #pragma unroll
        for (int i = 0; i < 8; i++) {
            int c   = tid + i * 128;
            int row = c >> 3, kq = c & 7;
            int m = m0 + row, kg = kt + kq * 8;
            const __half* src = A;
            int sz = 0;
            if (m < M && kg < KbA) {
                if (MODE == 1)
                    src = (kg < DD) ? &A[(size_t)m * DD + kg]
                                    : &A2[(size_t)m * DD + (kg - DD)];
                else
                    src = &A[(size_t)m * lda + kg];
                sz = 16;
            }
            cp_async16(abase + (row * HSTRIDE + kq * 8) * 2, src, sz);
        }
        unsigned int bbase = smB_u + st * (HSTAGE * 2);
        #pragma unroll
        for (int i = 0; i < 8; i++) {
            int c   = tid + i * 128;
            int row = c >> 3, kq = c & 7;
            int n = n0 + row, kg = kt + kq * 8;
            const __half* src = B;
            int sz = 0;
            if (n < N && kg < KbB) {
                src = &B[(size_t)n * ldb + kg];
                sz = 16;
            }
            cp_async16(bbase + (row * HSTRIDE + kq * 8) * 2, src, sz);
        }
    };

    auto compute = [&](int st) {
        const __half* Ab = sm + st * HSTAGE;
        const __half* Bb = sm + HB_BASE + st * HSTAGE;
        #pragma unroll
        for (int ks = 0; ks < 4; ks++) {
            const int k0 = ks * 16;
            unsigned int a[4][4], bf[8][2];
            #pragma unroll
            for (int mt = 0; mt < 4; mt++) {
                int ar = wm + mt * 16 + gid;
                a[mt][0] = *(const unsigned int*)(Ab + ar       * HSTRIDE + k0 + tg * 2);
                a[mt][1] = *(const unsigned int*)(Ab + (ar + 8) * HSTRIDE + k0 + tg * 2);
                a[mt][2] = *(const unsigned int*)(Ab + ar       * HSTRIDE + k0 + tg * 2 + 8);
                a[mt][3] = *(const unsigned int*)(Ab + (ar + 8) * HSTRIDE + k0 + tg * 2 + 8);
            }
            #pragma unroll
            for (int nt = 0; nt < 8; nt++) {
                if (n0 + wn + nt * 8 < N) {          // warp-uniform guard
                    int bc = wn + nt * 8 + gid;
                    bf[nt][0] = *(const unsigned int*)(Bb + bc * HSTRIDE + k0 + tg * 2);
                    bf[nt][1] = *(const unsigned int*)(Bb + bc * HSTRIDE + k0 + tg * 2 + 8);
                }
            }
            #pragma unroll
            for (int mt = 0; mt < 4; mt++)
                #pragma unroll
                for (int nt = 0; nt < 8; nt++) {
                    if (n0 + wn + nt * 8 < N) {      // warp-uniform guard
                        asm volatile(
                            "mma.sync.aligned.m16n8k16.row.col.f32.f16.f16.f32 "
                            "{%0,%1,%2,%3}, {%4,%5,%6,%7}, {%8,%9}, {%0,%1,%2,%3};\n"
                            : "+f"(acc[mt][nt][0]), "+f"(acc[mt][nt][1]),
                              "+f"(acc[mt][nt][2]), "+f"(acc[mt][nt][3])
                            : "r"(a[mt][0]), "r"(a[mt][1]), "r"(a[mt][2]), "r"(a[mt][3]),
                              "r"(bf[nt][0]), "r"(bf[nt][1]));
                    }
                }
        }
    };

    // ---- 2-stage pipeline, one sync per tile ----
    stage(0, 0);
    cp_commit();

    int st = 0;
    for (int t = 0; t < Ktiles; t++) {
        cp_wait<0>();
        __syncthreads();
        if (t + 1 < Ktiles) {
            stage((t + 1) * KT, st ^ 1);
            cp_commit();
        }
        compute(st);
        st ^= 1;
    }

    // ---- epilogue ----
    #pragma unroll
    for (int mt = 0; mt < 4; mt++) {
        #pragma unroll
        for (int nt = 0; nt < 8; nt++) {
            int row0 = m0 + wm + mt * 16 + gid;
            int col0 = n0 + wn + nt * 8 + tg * 2;
            #pragma unroll
            for (int q = 0; q < 4; q++) {
                int row = row0 + (q >> 1) * 8;
                int col = col0 + (q & 1);
                if (row < M && col < N) {
                    float v = acc[mt][nt][q];
                    if (ADD_BIAS) v += bias[col];
                    if (OUT == 0) {
                        ((float*)Cv)[(size_t)blockIdx.z * sC + (size_t)row * N + col] = v;
                    } else {
                        ((__half*)Cv)[(size_t)blockIdx.z * sC + (size_t)row * N + col] =
                            __float2half(v);
                    }
                }
            }
        }
    }
}

// ---------------------------------------------------------------------------
// Row softmax over 999 fp32 logits + scatter into fp16 (N x N), zero diagonal.
// ---------------------------------------------------------------------------
__global__ __launch_bounds__(256)
void softmax_scatter_kernel(const float* __restrict__ logits,
                            __half* __restrict__ S)
{
    const int i = blockIdx.x;
    const int b = blockIdx.y;
    const float* __restrict__ row = logits + ((size_t)(b * NN + i)) * NM1;
    __half* __restrict__ o = S + ((size_t)(b * NN + i)) * NN;

    __shared__ float sh[8];
    const int tid = threadIdx.x;
    const int lane = tid & 31, warp = tid >> 5;

    float rv[4];
    #pragma unroll
    for (int p = 0; p < 4; p++) {
        int k = tid + 256 * p;
        rv[p] = (k < NM1) ? row[k] : -1e30f;
    }

    float m = -1e30f;
    #pragma unroll
    for (int p = 0; p < 4; p++) m = fmaxf(m, rv[p]);
    #pragma unroll
    for (int off = 16; off; off >>= 1) m = fmaxf(m, __shfl_xor_sync(0xffffffffu, m, off));
    if (lane == 0) sh[warp] = m;
    __syncthreads();
    if (warp == 0) {
        float t = (lane < 8) ? sh[lane] : -1e30f;
        #pragma unroll
        for (int off = 16; off; off >>= 1) t = fmaxf(t, __shfl_xor_sync(0xffffffffu, t, off));
        if (lane == 0) sh[0] = t;
    }
    __syncthreads();
    m = sh[0];
    __syncthreads();

    float s = 0.f;
    float ev[4];
    #pragma unroll
    for (int p = 0; p < 4; p++) {
        int k = tid + 256 * p;
        float e = (k < NM1) ? __expf(rv[p] - m) : 0.f;
        ev[p] = e;
        s += e;
    }
    #pragma unroll
    for (int off = 16; off; off >>= 1) s += __shfl_xor_sync(0xffffffffu, s, off);
    if (lane == 0) sh[warp] = s;
    __syncthreads();
    if (warp == 0) {
        float t = (lane < 8) ? sh[lane] : 0.f;
        #pragma unroll
        for (int off = 16; off; off >>= 1) t += __shfl_xor_sync(0xffffffffu, t, off);
        if (lane == 0) sh[0] = t;
    }
    __syncthreads();
    const float inv = 1.f / sh[0];

    #pragma unroll
    for (int p = 0; p < 4; p++) {
        int k = tid + 256 * p;
        if (k < NM1) {
            int j = (k < i) ? k : k + 1;
            o[j] = __float2half(ev[p] * inv);
        }
    }
    if (tid == 0) o[i] = __float2half(0.f);
}

// ---------------------------------------------------------------------------
// Heads epilogue: out[r][c] from ho (32000 x 75), biases, anchors.
// ---------------------------------------------------------------------------
__global__ __launch_bounds__(256)
void heads_epilogue_kernel(const float* __restrict__ ho,
                           const float* __restrict__ cls_b,
                           const float* __restrict__ reg_b,
                           const float* __restrict__ anchors,
                           float* __restrict__ out)
{
    int idx = blockIdx.x * blockDim.x + threadIdx.x;
    if (idx >= BB * NN * OUTC) return;
    int c = idx % OUTC;
    int r = idx / OUTC;
    int n = r % NN;
    float v;
    if (c < 2)       v = ho[(size_t)r * HN + c] + cls_b[c];
    else if (c < 4)  v = anchors[n * OUTC + c];
    else             v = ho[(size_t)r * HN + (c - 2)] + reg_b[c - 4]
                         + anchors[n * OUTC + c];
    out[idx] = v;
}

// ---------------------------------------------------------------------------
// Launch
// ---------------------------------------------------------------------------
extern "C" void kernel_launch(void* const* d_in, const int* in_sizes, int n_in,
                              void* d_out, int out_size)
{
    const float* fv      = (const float*)d_in[0];
    const float* attn_w  = (const float*)d_in[1];
    const float* attn_b  = (const float*)d_in[2];
    const float* cls_w   = (const float*)d_in[3];
    const float* cls_b   = (const float*)d_in[4];
    const float* reg_w   = (const float*)d_in[5];
    const float* reg_b   = (const float*)d_in[6];
    const float* anchors = (const float*)d_in[7];
    const int*   z       = (const int*)d_in[8];
    const int*   y       = (const int*)d_in[9];
    const int*   x       = (const int*)d_in[10];
    const void*  mask    = d_in[11];
    float* out = (float*)d_out;

    __half *feat, *featT, *S, *att, *WT, *BtT;
    float *logits, *ho;
    cudaGetSymbolAddress((void**)&feat,   g_feat);
    cudaGetSymbolAddress((void**)&featT,  g_featT);
    cudaGetSymbolAddress((void**)&logits, g_logits);
    cudaGetSymbolAddress((void**)&S,      g_S);
    cudaGetSymbolAddress((void**)&att,    g_att);
    cudaGetSymbolAddress((void**)&ho,     g_ho);
    cudaGetSymbolAddress((void**)&WT,     g_WT);
    cudaGetSymbolAddress((void**)&BtT,    g_BtT);

    static int attr_done = 0;
    if (!attr_done) {
        cudaFuncSetAttribute(gemm_fp16_kernel<0, true,  0>,
                             cudaFuncAttributeMaxDynamicSharedMemorySize, GSMEM);
        cudaFuncSetAttribute(gemm_fp16_kernel<0, false, 1>,
                             cudaFuncAttributeMaxDynamicSharedMemorySize, GSMEM);
        cudaFuncSetAttribute(gemm_fp16_kernel<1, false, 0>,
                             cudaFuncAttributeMaxDynamicSharedMemorySize, GSMEM);
        attr_done = 1;
    }

    // 1) mask dtype detection
    detect_mask_kernel<<<1, 256>>>((const unsigned int*)mask, 190000);

    // 2) gather (fp16 feat)
    {
        int total = BB * NN * DD;
        gather_kernel<<<(total + 255) / 256, 256>>>(fv, z, y, x, mask, feat, total);
    }

    // 2b) transpose feat -> featT; attn_w^T; heads W^T (all fp16)
    {
        dim3 grid(DD / 32, (NN + 31) / 32, BB);
        transpose_kernel<<<grid, 256>>>(feat, featT);
    }
    prep_attnwT_kernel<<<(NM1 * DD + 255) / 256, 256>>>(attn_w, BtT);
    pack_w_kernel<<<(HN * 2 * DD + 255) / 256, 256>>>(cls_w, reg_w, WT);

    // 3) logits = feat @ attn_w + attn_b   (1000x999, K=768 -> 12 tiles; fp32 out)
    {
        dim3 grid((NM1 + 127) / 128, (NN + 127) / 128, BB);
        gemm_fp16_kernel<0, true, 0><<<grid, 128, GSMEM>>>(
            feat, nullptr, BtT, attn_b, (void*)logits,
            NN, NM1, DD / KT, DD, DD, DD, DD,
            (size_t)NN * DD, 0, (size_t)NN * NM1);
    }

    // 4) softmax + scatter (fp16 S)
    {
        dim3 grid(NN, BB);
        softmax_scatter_kernel<<<grid, 256>>>(logits, S);
    }

    // 5) att = S @ feat   (1000x768, K=1000 -> 16 tiles, zero-fill; fp16 out)
    {
        dim3 grid((DD + 127) / 128, (NN + 127) / 128, BB);
        gemm_fp16_kernel<0, false, 1><<<grid, 128, GSMEM>>>(
            S, nullptr, featT, nullptr, (void*)att,
            NN, DD, 16, NN, NN, NN, NN,
            (size_t)NN * NN, (size_t)DD * NN, (size_t)NN * DD);
    }

    // 6) heads GEMM: [att|feat] (32000 x 1536) @ WT^T (75 cols), K=1536 -> 24 tiles
    {
        dim3 grid(1, (BB * NN + 127) / 128, 1);
        gemm_fp16_kernel<1, false, 0><<<grid, 128, GSMEM>>>(
            att, feat, WT, nullptr, (void*)ho,
            BB * NN, HN, 24, 2 * DD, 2 * DD, 2 * DD, 2 * DD,
            0, 0, 0);
    }

    // 7) heads epilogue
    {
        int total = BB * NN * OUTC;
        heads_epilogue_kernel<<<(total + 255) / 256, 256>>>(ho, cls_b, reg_b,
                                                            anchors, out);
    }
}